// round 2
// baseline (speedup 1.0000x reference)
#include <cuda_runtime.h>
#include <cstdint>

// Problem constants (fixed by the reference: M=4 molecules, N=2048 atoms)
#define NATOMS 2048
#define NMOL   4
#define NPAIR  2096128            // N*(N-1)/2
#define MP     ((size_t)NMOL * (size_t)NPAIR)   // 8,384,512

// Output layout (flattened concat of the reference tuple, float32):
//   [0,           2*MP)  : atom_index12  ([2, M*P] row-major, as float)
//   [2*MP,        5*MP)  : shift_values  ([M*P, 3], all zeros)
//   [5*MP,        6*MP)  : mask          ([M*P], 1.0/0.0)

__device__ __forceinline__ int row_offset(int i) {
    // offset of row i in triu_indices(N, k=1): sum_{t<i}(N-1-t) = i*(2N-1-i)/2
    return (i * (2 * NATOMS - 1 - i)) >> 1;
}

__global__ __launch_bounds__(256)
void fullpairwise_kernel(const int*   __restrict__ species,
                         const float* __restrict__ coords,
                         float*       __restrict__ out)
{
    const int m  = blockIdx.y;                               // molecule
    const int t  = blockIdx.x * blockDim.x + threadIdx.x;    // vec-unit id
    const int p0 = t * 4;                                    // first pair idx
    // grid sized exactly: P/4 = 524032 = 2047 * 256, no bounds check needed

    // --- invert triangular index: find row i with row_offset(i) <= p0 ---
    // disc = (2N-1)^2 - 8*p0 ; both < 2^24 so the float conversion is exact,
    // and sqrtf is correctly rounded -> estimate within 1, fixed up below.
    const int   disc = 16769025 - 8 * p0;                    // 4095^2 - 8p
    int i = (int)((4095.0f - sqrtf((float)disc)) * 0.5f);
    if (i < 0) i = 0;
    while (row_offset(i + 1) <= p0) ++i;
    while (row_offset(i) > p0)      --i;
    int j = i + 1 + (p0 - row_offset(i));

    const float* cm = coords  + (size_t)m * NATOMS * 3;
    const int*   sm = species + (size_t)m * NATOMS;

    const float cut2 = 5.2f * 5.2f;   // fp32, matches jnp.asarray(5.2,f32)**2

    float4 vi, vj, vm;
    float* fi = &vi.x; float* fj = &vj.x; float* fm = &vm.x;

    #pragma unroll
    for (int k = 0; k < 4; ++k) {
        const float xi = __ldg(&cm[3 * i + 0]);
        const float yi = __ldg(&cm[3 * i + 1]);
        const float zi = __ldg(&cm[3 * i + 2]);
        const float xj = __ldg(&cm[3 * j + 0]);
        const float yj = __ldg(&cm[3 * j + 1]);
        const float zj = __ldg(&cm[3 * j + 2]);
        const float dx = xi - xj, dy = yi - yj, dz = zi - zj;
        // exact fp32, no FMA contraction, jnp reduction order ((x^2+y^2)+z^2)
        const float d2 = __fadd_rn(__fadd_rn(__fmul_rn(dx, dx),
                                             __fmul_rn(dy, dy)),
                                   __fmul_rn(dz, dz));
        const bool valid = (__ldg(&sm[i]) != -1) && (__ldg(&sm[j]) != -1);
        const bool ok    = valid && (d2 <= cut2);

        fi[k] = (float)(i + m * NATOMS);
        fj[k] = (float)(j + m * NATOMS);
        fm[k] = ok ? 1.0f : 0.0f;

        // advance to next pair (row-major triu order)
        if (++j == NATOMS) { ++i; j = i + 1; }   // final advance unused OOB-safe
    }

    const size_t q0 = (size_t)m * NPAIR + (size_t)p0;

    // atom_index12 row 0 (i indices) and row 1 (j indices)
    *reinterpret_cast<float4*>(out + q0)       = vi;
    *reinterpret_cast<float4*>(out + MP + q0)  = vj;

    // shift_values: 12 zero floats for pairs q0..q0+3
    const float4 z = make_float4(0.f, 0.f, 0.f, 0.f);
    float4* zp = reinterpret_cast<float4*>(out + 2 * MP + 3 * q0);
    zp[0] = z; zp[1] = z; zp[2] = z;

    // mask
    *reinterpret_cast<float4*>(out + 5 * MP + q0) = vm;
}

extern "C" void kernel_launch(void* const* d_in, const int* in_sizes, int n_in,
                              void* d_out, int out_size)
{
    const int*   species = (const int*)  d_in[0];
    const float* coords  = (const float*)d_in[1];
    float*       out     = (float*)d_out;

    dim3 block(256);
    dim3 grid((NPAIR / 4 + 255) / 256, NMOL);   // (2047, 4), exact coverage
    fullpairwise_kernel<<<grid, block>>>(species, coords, out);
}

// round 3
// speedup vs baseline: 1.3680x; 1.3680x over previous
#include <cuda_runtime.h>
#include <cstdint>
#include <math_constants.h>

// Problem constants (fixed by the reference: M=4 molecules, N=2048 atoms)
#define NATOMS 2048
#define NMOL   4
#define NPAIR  2096128                          // N*(N-1)/2
#define MP     ((size_t)NMOL * (size_t)NPAIR)   // 8,384,512

// Output layout (flattened concat of the reference tuple, float32):
//   [0,    2*MP) : atom_index12 ([2, M*P] row-major, as float)
//   [2*MP, 5*MP) : shift_values ([M*P, 3], all zeros)
//   [5*MP, 6*MP) : mask         ([M*P], 1.0/0.0)

// Scratch: coords packed as float4 per atom, NaN-filled where species == -1.
__device__ float4 g_c4[NMOL * NATOMS];

__device__ __forceinline__ int row_offset(int i) {
    // offset of row i in triu_indices(N, k=1): i*(2N-1-i)/2
    return (i * (2 * NATOMS - 1 - i)) >> 1;
}

__global__ void prep_kernel(const int*   __restrict__ species,
                            const float* __restrict__ coords)
{
    const int a = blockIdx.x * blockDim.x + threadIdx.x;   // 0 .. NMOL*NATOMS-1
    float x = coords[3 * a + 0];
    float y = coords[3 * a + 1];
    float z = coords[3 * a + 2];
    if (species[a] == -1) { x = CUDART_NAN_F; y = CUDART_NAN_F; z = CUDART_NAN_F; }
    g_c4[a] = make_float4(x, y, z, 0.0f);
}

__global__ __launch_bounds__(256)
void fullpairwise_kernel(float* __restrict__ out)
{
    const int m    = blockIdx.y;
    const int tid  = threadIdx.x;
    const int base = blockIdx.x * 1024 + tid;      // pair id for k=0
    // grid.x = NPAIR/1024 = 2047 exactly -> no bounds checks

    const float4* __restrict__ cm = g_c4 + m * NATOMS;
    const float cut2 = 5.2f * 5.2f;                // fp32, matches jnp
    const float foff = (float)(m * NATOMS);

    // ---- zeros region: decoupled flat fill, fully coalesced STG.128 ----
    {
        const size_t zbase = 2 * MP + 3 * ((size_t)m * NPAIR + (size_t)blockIdx.x * 1024);
        float4* zp = reinterpret_cast<float4*>(out + zbase);   // 768 float4 per block
        const float4 z4 = make_float4(0.f, 0.f, 0.f, 0.f);
        zp[tid]       = z4;
        zp[tid + 256] = z4;
        zp[tid + 512] = z4;
    }

    // ---- pair work: lane-consecutive p => coalesced j loads & scalar stores ----
    #pragma unroll
    for (int k = 0; k < 4; ++k) {
        const int p = base + k * 256;

        // invert triangular index: disc = 4095^2 - 8p < 2^24, exact in fp32;
        // sqrtf estimate fixed up to exactness by the +/-1 loops.
        const int disc = 16769025 - 8 * p;
        int i = (int)((4095.0f - sqrtf((float)disc)) * 0.5f);
        if (i < 0) i = 0;
        while (row_offset(i + 1) <= p) ++i;
        while (row_offset(i) > p)      --i;
        const int j = i + 1 + (p - row_offset(i));

        const float4 ci = __ldg(&cm[i]);   // warp-uniform-ish broadcast
        const float4 cj = __ldg(&cm[j]);   // lane-consecutive -> coalesced

        const float dx = ci.x - cj.x;
        const float dy = ci.y - cj.y;
        const float dz = ci.z - cj.z;
        // exact fp32, no FMA contraction, jnp reduction order ((x^2+y^2)+z^2);
        // NaN (padded atoms) compares false, matching the reference mask.
        const float d2 = __fadd_rn(__fadd_rn(__fmul_rn(dx, dx),
                                             __fmul_rn(dy, dy)),
                                   __fmul_rn(dz, dz));
        const float ok = (d2 <= cut2) ? 1.0f : 0.0f;

        const size_t q = (size_t)m * NPAIR + (size_t)p;
        out[q]          = (float)i + foff;   // atom_index12 row 0
        out[MP + q]     = (float)j + foff;   // atom_index12 row 1
        out[5 * MP + q] = ok;                // mask
    }
}

extern "C" void kernel_launch(void* const* d_in, const int* in_sizes, int n_in,
                              void* d_out, int out_size)
{
    const int*   species = (const int*)  d_in[0];
    const float* coords  = (const float*)d_in[1];
    float*       out     = (float*)d_out;

    prep_kernel<<<(NMOL * NATOMS) / 256, 256>>>(species, coords);

    dim3 grid(NPAIR / 1024, NMOL);   // (2047, 4), exact coverage
    fullpairwise_kernel<<<grid, 256>>>(out);
}